// round 6
// baseline (speedup 1.0000x reference)
#include <cuda_runtime.h>
#include <cuda_fp16.h>
#include <cstdint>

// Problem constants
#define S_    8
#define U_    8
#define K_    12
#define NEG_  17
#define ZD    64
#define CD    256
#define T_    1140
#define LEN   1128
#define SU    64
#define TOTPOS 72192

// ---------------- scratch ----------------
__device__ float  g_Wc[(size_t)K_ * TOTPOS * ZD];   // ~222 MB
__device__ double g_loss[K_];
__device__ double g_acc[K_];

__global__ void zero_accum() {
    int i = threadIdx.x;
    if (i < K_) { g_loss[i] = 0.0; g_acc[i] = 0.0; }
}

// ================= helpers =================
__device__ __forceinline__ uint32_t smem_u32(const void* p) {
    uint32_t a;
    asm("{ .reg .u64 t; cvta.to.shared.u64 t, %1; cvt.u32.u64 %0, t; }" : "=r"(a) : "l"(p));
    return a;
}

#define SW128(off) ((off) ^ (((off) >> 3) & 0x70))

__device__ __forceinline__ void ldm_x4(uint32_t* r, uint32_t addr) {
    asm volatile("ldmatrix.sync.aligned.m8n8.x4.shared.b16 {%0,%1,%2,%3}, [%4];"
                 : "=r"(r[0]), "=r"(r[1]), "=r"(r[2]), "=r"(r[3]) : "r"(addr));
}

__device__ __forceinline__ void mma16816(float* c, const uint32_t* a, const uint32_t* b) {
    asm volatile(
        "mma.sync.aligned.m16n8k16.row.col.f32.f16.f16.f32 "
        "{%0,%1,%2,%3}, {%4,%5,%6,%7}, {%8,%9}, {%0,%1,%2,%3};"
        : "+f"(c[0]), "+f"(c[1]), "+f"(c[2]), "+f"(c[3])
        : "r"(a[0]), "r"(a[1]), "r"(a[2]), "r"(a[3]), "r"(b[0]), "r"(b[1]));
}

// ================= split-fp16 GEMM via mma.sync (plain sm_100 legal) =================
// Block computes Wc tile [128 l-rows x 64 z-cols] for one (k, su, l-tile).
// A = c rows (M=128, K=256), B = W[k] (N=64, K=256); both stored in smem as
// fp16 hi/lo pairs, K-major, SW128 blocked-atom layout (atom = 8 rows x 128B).
// D = Ah*Bh + Ah*Bl + Al*Bh accumulated in fp32 registers (error ~2^-22).

#define OFF_AHI  0
#define OFF_ALO  65536
#define OFF_BHI  131072
#define OFF_BLO  (131072 + 32768)
#define SMEM_TOTAL_GEMM (131072 + 65536)

__device__ __forceinline__ void cvt8_hilo(const float* __restrict__ p, uint4& hi, uint4& lo) {
    float4 a = *(const float4*)p;
    float4 b = *(const float4*)(p + 4);
    float f[8] = {a.x, a.y, a.z, a.w, b.x, b.y, b.z, b.w};
    uint32_t hu[8], lu[8];
#pragma unroll
    for (int i = 0; i < 8; i++) {
        __half h = __float2half_rn(f[i]);
        float  r = f[i] - __half2float(h);
        __half l = __float2half_rn(r);
        hu[i] = (uint32_t)__half_as_ushort(h);
        lu[i] = (uint32_t)__half_as_ushort(l);
    }
    hi.x = hu[0] | (hu[1] << 16); hi.y = hu[2] | (hu[3] << 16);
    hi.z = hu[4] | (hu[5] << 16); hi.w = hu[6] | (hu[7] << 16);
    lo.x = lu[0] | (lu[1] << 16); lo.y = lu[2] | (lu[3] << 16);
    lo.z = lu[4] | (lu[5] << 16); lo.w = lu[6] | (lu[7] << 16);
}

// pre-swizzle byte offsets into blocked-atom layouts
__device__ __forceinline__ uint32_t a_off(int row, int col) {      // 128 rows: 16 atoms/atom-col
    return (uint32_t)(((row >> 3) + (col >> 6) * 16) * 1024 + (row & 7) * 128 + (col & 63) * 2);
}
__device__ __forceinline__ uint32_t b_off(int row, int col) {      // 64 rows: 8 atoms/atom-col
    return (uint32_t)(((row >> 3) + (col >> 6) * 8) * 1024 + (row & 7) * 128 + (col & 63) * 2);
}
// swizzled ldmatrix row address: bits[9:7] of offset == row&7 (col&63)*2 < 128, so
// SW128 reduces to XOR of ((row&7)<<4) into the col term.
__device__ __forceinline__ uint32_t a_addr(uint32_t base, int row, int col) {
    uint32_t rowp = (uint32_t)((row >> 3) * 1024 + (row & 7) * 128);
    uint32_t colp = (uint32_t)(((col >> 6) << 14) | ((((col & 63) << 1)) ^ ((row & 7) << 4)));
    return base + rowp + colp;
}
__device__ __forceinline__ uint32_t b_addr(uint32_t base, int row, int col) {
    uint32_t rowp = (uint32_t)((row >> 3) * 1024 + (row & 7) * 128);
    uint32_t colp = (uint32_t)(((col >> 6) << 13) | ((((col & 63) << 1)) ^ ((row & 7) << 4)));
    return base + rowp + colp;
}

__global__ __launch_bounds__(256) void gemm_wc_mma(const float* __restrict__ C,
                                                   const float* __restrict__ W,
                                                   const float* __restrict__ Bias) {
    extern __shared__ char smem[];
    const uint32_t sb = smem_u32(smem);
    const int tid  = threadIdx.x;
    const int wid  = tid >> 5;
    const int lane = tid & 31;

    const int k  = blockIdx.x;
    const int l0 = blockIdx.y * 128;
    const int su = blockIdx.z;

    // ---- load + convert A: each thread does half a row (128 halves = 16 chunks of 8)
    {
        const int row = tid >> 1;
        const int cb  = (tid & 1) * 128;
        int rr = l0 + row; if (rr > T_ - 1) rr = T_ - 1;   // clamp; rows >= LEN never stored
        const float* arow = C + ((size_t)su * T_ + rr) * CD;
#pragma unroll
        for (int c8 = 0; c8 < 16; c8++) {
            const int col = cb + c8 * 8;
            uint4 hi, lo;
            cvt8_hilo(arow + col, hi, lo);
            const uint32_t off = SW128(a_off(row, col));
            *(uint4*)(smem + OFF_AHI + off) = hi;
            *(uint4*)(smem + OFF_ALO + off) = lo;
        }
    }
    // ---- load + convert B = W[k]: each thread a quarter row (64 halves = 8 chunks)
    {
        const int row = tid >> 2;
        const int cb  = (tid & 3) * 64;
        const float* brow = W + ((size_t)k * ZD + row) * CD;
#pragma unroll
        for (int c8 = 0; c8 < 8; c8++) {
            const int col = cb + c8 * 8;
            uint4 hi, lo;
            cvt8_hilo(brow + col, hi, lo);
            const uint32_t off = SW128(b_off(row, col));
            *(uint4*)(smem + OFF_BHI + off) = hi;
            *(uint4*)(smem + OFF_BLO + off) = lo;
        }
    }
    __syncthreads();

    // ---- warp tiling: 4 m-warps x 2 n-warps; each warp 32x32
    const int warp_m = wid & 3;
    const int warp_n = wid >> 2;
    const int row0 = warp_m * 32;
    const int n0   = warp_n * 32;

    float acc[2][4][4];
#pragma unroll
    for (int i = 0; i < 2; i++)
#pragma unroll
        for (int j = 0; j < 4; j++)
#pragma unroll
            for (int q = 0; q < 4; q++) acc[i][j][q] = 0.0f;

    const int g = lane >> 3;            // ldmatrix address group 0..3
    const int lr = lane & 7;
    // A x4 lane pattern: row += (g&1)*8, col += (g&2)*4
    const int a_radd = (g & 1) * 8 + lr;
    const int a_cadd = (g & 2) * 4;
    // B x4 lane pattern: row += (g>>1)*8, col += (g&1)*8
    const int b_radd = (g >> 1) * 8 + lr;
    const int b_cadd = (g & 1) * 8;

    const uint32_t a_bases[3] = {sb + OFF_AHI, sb + OFF_AHI, sb + OFF_ALO};
    const uint32_t b_bases[3] = {sb + OFF_BHI, sb + OFF_BLO, sb + OFF_BHI};

#pragma unroll
    for (int p = 0; p < 3; p++) {
        const uint32_t ab = a_bases[p];
        const uint32_t bb = b_bases[p];
#pragma unroll
        for (int ks = 0; ks < 16; ks++) {
            const int k0 = ks * 16;
            uint32_t af[2][4], bf[2][4];
            ldm_x4(af[0], a_addr(ab, row0 +      a_radd, k0 + a_cadd));
            ldm_x4(af[1], a_addr(ab, row0 + 16 + a_radd, k0 + a_cadd));
            ldm_x4(bf[0], b_addr(bb, n0 +       b_radd, k0 + b_cadd));
            ldm_x4(bf[1], b_addr(bb, n0 + 16 +  b_radd, k0 + b_cadd));
#pragma unroll
            for (int mf = 0; mf < 2; mf++) {
                mma16816(acc[mf][0], af[mf], &bf[0][0]);
                mma16816(acc[mf][1], af[mf], &bf[0][2]);
                mma16816(acc[mf][2], af[mf], &bf[1][0]);
                mma16816(acc[mf][3], af[mf], &bf[1][2]);
            }
        }
    }

    // ---- epilogue: add bias, store fp32 to g_Wc
    const int tr = lane >> 2;          // 0..7
    const int tc = (lane & 3) * 2;     // 0,2,4,6
    float* outbase = g_Wc + ((size_t)k * TOTPOS + (size_t)su * LEN) * ZD;
#pragma unroll
    for (int mf = 0; mf < 2; mf++) {
#pragma unroll
        for (int nt = 0; nt < 4; nt++) {
            const int col = n0 + nt * 8 + tc;
            const float b0 = __ldg(Bias + k * ZD + col);
            const float b1 = __ldg(Bias + k * ZD + col + 1);
            int l = l0 + row0 + mf * 16 + tr;
            if (l < LEN) {
                float2 o = make_float2(acc[mf][nt][0] + b0, acc[mf][nt][1] + b1);
                *(float2*)(outbase + (size_t)l * ZD + col) = o;
            }
            l += 8;
            if (l < LEN) {
                float2 o = make_float2(acc[mf][nt][2] + b0, acc[mf][nt][3] + b1);
                *(float2*)(outbase + (size_t)l * ZD + col) = o;
            }
        }
    }
}

// ================= CPC loss (identical to R2-passing version) =================
#define BLOCKS_PER_K 2256

__global__ __launch_bounds__(256) void cpc_loss(const float* __restrict__ z,
                                                const int* __restrict__ batch_index,
                                                const int* __restrict__ seq_index) {
    const int wid  = threadIdx.x >> 5;
    const int lane = threadIdx.x & 31;
    const int grp  = lane >> 3;
    const int lg   = lane & 7;

    const int k   = blockIdx.x / BLOCKS_PER_K;
    const int rem = blockIdx.x % BLOCKS_PER_K;
    const int wg  = rem * 8 + wid;
    const int su  = wg / 282;
    const int l   = (wg % 282) * 4 + grp;
    const int s   = su >> 3;
    const int u   = su & 7;
    const int kshift = k + 1;

    const float* wc = g_Wc + ((size_t)k * TOTPOS + (size_t)su * LEN + l) * ZD;
    const float4 wa = *(const float4*)(wc + 4 * lg);
    const float4 wb = *(const float4*)(wc + 32 + 4 * lg);

    const float* zp = z + ((size_t)(su * T_ + l + kshift)) * ZD;
    float4 za = *(const float4*)(zp + 4 * lg);
    float4 zb = *(const float4*)(zp + 32 + 4 * lg);
    float v = wa.x * za.x + wa.y * za.y + wa.z * za.z + wa.w * za.w
            + wb.x * zb.x + wb.y * zb.y + wb.z * zb.z + wb.w * zb.w;
    v += __shfl_xor_sync(0xffffffffu, v, 1);
    v += __shfl_xor_sync(0xffffffffu, v, 2);
    v += __shfl_xor_sync(0xffffffffu, v, 4);
    const float pos = v * 0.125f;

    const int* bip = batch_index + (k * U_ + u) * NEG_;
    const int* sip = seq_index + ((size_t)((k * S_ + s) * U_ + u) * NEG_) * LEN + l;
    int bis[NEG_], sis[NEG_];
#pragma unroll
    for (int n = 0; n < NEG_; n++) {
        bis[n] = __ldg(bip + n);
        sis[n] = __ldg(sip + (size_t)n * LEN);
    }

    float m = pos, ssum = 1.0f, ok = 1.0f;
#pragma unroll
    for (int n = 0; n < NEG_; n++) {
        const float* zr = z + ((size_t)((s * 8 + bis[n]) * T_ + sis[n] + kshift)) * ZD;
        float4 na = *(const float4*)(zr + 4 * lg);
        float4 nb = *(const float4*)(zr + 32 + 4 * lg);
        float d = wa.x * na.x + wa.y * na.y + wa.z * na.z + wa.w * na.w
                + wb.x * nb.x + wb.y * nb.y + wb.z * nb.z + wb.w * nb.w;
        d += __shfl_xor_sync(0xffffffffu, d, 1);
        d += __shfl_xor_sync(0xffffffffu, d, 2);
        d += __shfl_xor_sync(0xffffffffu, d, 4);
        d *= 0.125f;
        if (d > pos) ok = 0.0f;
        if (d > m) { ssum = ssum * __expf(m - d) + 1.0f; m = d; }
        else       { ssum += __expf(d - m); }
    }

    float lt = m + __logf(ssum) - pos;

    lt += __shfl_xor_sync(0xffffffffu, lt, 8);
    lt += __shfl_xor_sync(0xffffffffu, lt, 16);
    ok += __shfl_xor_sync(0xffffffffu, ok, 8);
    ok += __shfl_xor_sync(0xffffffffu, ok, 16);

    __shared__ float sL[8], sA[8];
    if (lane == 0) { sL[wid] = lt; sA[wid] = ok; }
    __syncthreads();
    if (threadIdx.x == 0) {
        float L = 0.f, A = 0.f;
#pragma unroll
        for (int i = 0; i < 8; i++) { L += sL[i]; A += sA[i]; }
        atomicAdd(&g_loss[k], (double)L);
        atomicAdd(&g_acc[k], (double)A);
    }
}

__global__ void finalize(float* __restrict__ out, int out_size) {
    if (threadIdx.x == 0) {
        double tot = 0.0;
#pragma unroll
        for (int kk = 0; kk < K_; kk++) tot += g_loss[kk];
        if (out_size > 0) out[0] = (float)(tot / ((double)K_ * (double)TOTPOS));
#pragma unroll
        for (int kk = 0; kk < K_; kk++)
            if (1 + kk < out_size) out[1 + kk] = (float)(g_acc[kk] / (double)TOTPOS);
    }
}

// ---------------- launch ----------------
extern "C" void kernel_launch(void* const* d_in, const int* in_sizes, int n_in,
                              void* d_out, int out_size) {
    const float* z  = (const float*)d_in[0];
    const float* c  = (const float*)d_in[1];
    const float* W  = (const float*)d_in[2];
    const float* b  = (const float*)d_in[3];
    const int* bidx = (const int*)d_in[4];
    const int* sidx = (const int*)d_in[5];

    cudaFuncSetAttribute(gemm_wc_mma, cudaFuncAttributeMaxDynamicSharedMemorySize,
                         SMEM_TOTAL_GEMM);

    zero_accum<<<1, 32>>>();

    dim3 ggrid(K_, 9, SU);
    gemm_wc_mma<<<ggrid, 256, SMEM_TOTAL_GEMM>>>(c, W, b);

    cpc_loss<<<K_ * BLOCKS_PER_K, 256>>>(z, bidx, sidx);

    finalize<<<1, 32>>>((float*)d_out, out_size);
}

// round 7
// speedup vs baseline: 1.0968x; 1.0968x over previous
#include <cuda_runtime.h>
#include <cstdint>

// Problem constants
#define S_    8
#define U_    8
#define K_    12
#define NEG_  17
#define ZD    64
#define CD    256
#define T_    1140
#define LEN   1128
#define SU    64
#define TOTPOS 72192

__device__ double g_loss[K_];
__device__ double g_acc[K_];

__global__ void zero_accum() {
    int i = threadIdx.x;
    if (i < K_) { g_loss[i] = 0.0; g_acc[i] = 0.0; }
}

// ================= fused GEMM + CPC loss =================
// CTA = (kpair, l-tile, su). Phase 1: Wc tile [128 l x 128 n] (n = 2 k-slices of 64 z)
// via fp32 FFMA GEMM, result + bias -> smem. Phase 2: CPC loss for the 128 l x 2 k
// directly from smem (pos + 17 neg gathers from z, streaming logsumexp).
// Overlap: co-resident CTAs sit in different phases (FMA pipe vs L2), hiding each other.

#define AS_STRIDE 132
#define BS_STRIDE 132
#define WC_STRIDE 132
// float offsets into dynamic smem
#define OFF_AS 0
#define OFF_BS (16 * AS_STRIDE)
#define OFF_WC (2 * 16 * AS_STRIDE)
#define SMEM_BYTES ((OFF_WC + 128 * WC_STRIDE) * 4)   // 84,480 B

__global__ __launch_bounds__(256, 2) void fused_gemm_loss(
    const float* __restrict__ C,
    const float* __restrict__ W,
    const float* __restrict__ Bias,
    const float* __restrict__ z,
    const int* __restrict__ batch_index,
    const int* __restrict__ seq_index)
{
    extern __shared__ float smf[];
    float* As = smf + OFF_AS;   // [16][132]  As[kc][row]
    float* Bs = smf + OFF_BS;   // [16][132]  Bs[kc][n]
    float* wc = smf + OFF_WC;   // [128][132] Wc tile (+bias)

    const int tid = threadIdx.x;
    const int k0 = blockIdx.x * 2;     // k pair (fastest -> A-tile L2 reuse across kp)
    const int lt = blockIdx.y;         // 0..8
    const int su = blockIdx.z;         // 0..63
    const int l0 = lt * 128;

    // ---------------- phase 1: GEMM ----------------
    const int ty = tid >> 4;           // 0..15 -> rows ty*8..+8
    const int tx = tid & 15;           // 0..15 -> cols tx*8..+8

    float acc[8][8];
#pragma unroll
    for (int i = 0; i < 8; i++)
#pragma unroll
        for (int j = 0; j < 8; j++) acc[i][j] = 0.0f;

    for (int kt = 0; kt < CD; kt += 16) {
        // A tile: 128 rows x 16 cols = 512 float4, 2 per thread
#pragma unroll
        for (int r = 0; r < 2; r++) {
            int f = r * 256 + tid;
            int row = f >> 2, c4 = f & 3;
            int rr = l0 + row; if (rr > T_ - 1) rr = T_ - 1;   // clamp (junk rows never used)
            const float4 v = *(const float4*)(C + ((size_t)su * T_ + rr) * CD + kt + c4 * 4);
            As[(c4 * 4 + 0) * AS_STRIDE + row] = v.x;
            As[(c4 * 4 + 1) * AS_STRIDE + row] = v.y;
            As[(c4 * 4 + 2) * AS_STRIDE + row] = v.z;
            As[(c4 * 4 + 3) * AS_STRIDE + row] = v.w;
        }
        // B tile: 128 n-rows (2 k-slices of W) x 16 cols, 2 float4 per thread
#pragma unroll
        for (int r = 0; r < 2; r++) {
            int f = r * 256 + tid;
            int n = f >> 2, c4 = f & 3;
            const float* brow = W + ((size_t)(k0 + (n >> 6)) * ZD + (n & 63)) * CD;
            const float4 v = *(const float4*)(brow + kt + c4 * 4);
            Bs[(c4 * 4 + 0) * BS_STRIDE + n] = v.x;
            Bs[(c4 * 4 + 1) * BS_STRIDE + n] = v.y;
            Bs[(c4 * 4 + 2) * BS_STRIDE + n] = v.z;
            Bs[(c4 * 4 + 3) * BS_STRIDE + n] = v.w;
        }
        __syncthreads();

#pragma unroll
        for (int kk = 0; kk < 16; kk++) {
            float4 a0 = *(const float4*)&As[kk * AS_STRIDE + ty * 8];
            float4 a1 = *(const float4*)&As[kk * AS_STRIDE + ty * 8 + 4];
            float4 b0 = *(const float4*)&Bs[kk * BS_STRIDE + tx * 8];
            float4 b1 = *(const float4*)&Bs[kk * BS_STRIDE + tx * 8 + 4];
            float a[8] = {a0.x, a0.y, a0.z, a0.w, a1.x, a1.y, a1.z, a1.w};
            float b[8] = {b0.x, b0.y, b0.z, b0.w, b1.x, b1.y, b1.z, b1.w};
#pragma unroll
            for (int i = 0; i < 8; i++)
#pragma unroll
                for (int j = 0; j < 8; j++) acc[i][j] += a[i] * b[j];
        }
        __syncthreads();
    }

    // dump Wc tile (+bias) to smem
    {
        float bias[8];
#pragma unroll
        for (int j = 0; j < 8; j++) {
            int n = tx * 8 + j;
            bias[j] = __ldg(Bias + (k0 + (n >> 6)) * ZD + (n & 63));
        }
#pragma unroll
        for (int i = 0; i < 8; i++) {
            int row = ty * 8 + i;
#pragma unroll
            for (int j = 0; j < 8; j++)
                wc[row * WC_STRIDE + tx * 8 + j] = acc[i][j] + bias[j];
        }
    }
    __syncthreads();

    // ---------------- phase 2: CPC loss ----------------
    // 32 groups of 8 lanes; group g handles pairs g*8+j, j=0..7; pair -> (lrow, kh).
    const int lane = tid & 31;
    const int wid  = tid >> 5;
    const int g8   = tid >> 3;
    const int lg   = tid & 7;
    const unsigned gmask = 0xFFu << ((lane >> 3) * 8);
    const int s = su >> 3, u = su & 7;

    float lts[2] = {0.f, 0.f};
    float oks[2] = {0.f, 0.f};

#pragma unroll 1
    for (int j = 0; j < 8; j++) {
        const int pair = g8 * 8 + j;
        const int lrow = pair >> 1;
        const int kh   = pair & 1;
        const int l    = l0 + lrow;
        if (l < LEN) {
            const int k = k0 + kh;
            const int kshift = k + 1;

            const float* wrow = wc + lrow * WC_STRIDE + kh * 64;
            const float4 wa = *(const float4*)(wrow + 4 * lg);
            const float4 wb = *(const float4*)(wrow + 32 + 4 * lg);

            // positive: z[su, l + kshift, :]
            const float* zp = z + ((size_t)(su * T_ + l + kshift)) * ZD;
            float4 za = *(const float4*)(zp + 4 * lg);
            float4 zb = *(const float4*)(zp + 32 + 4 * lg);
            float v = wa.x * za.x + wa.y * za.y + wa.z * za.z + wa.w * za.w
                    + wb.x * zb.x + wb.y * zb.y + wb.z * zb.z + wb.w * zb.w;
            v += __shfl_xor_sync(gmask, v, 1);
            v += __shfl_xor_sync(gmask, v, 2);
            v += __shfl_xor_sync(gmask, v, 4);
            const float pos = v * 0.125f;

            const int* bip = batch_index + (k * U_ + u) * NEG_;
            const int* sip = seq_index + ((size_t)((k * S_ + s) * U_ + u) * NEG_) * LEN + l;
            int bis[NEG_], sis[NEG_];
#pragma unroll
            for (int n = 0; n < NEG_; n++) {
                bis[n] = __ldg(bip + n);
                sis[n] = __ldg(sip + (size_t)n * LEN);
            }

            float m = pos, ssum = 1.0f, ok = 1.0f;
#pragma unroll
            for (int n = 0; n < NEG_; n++) {
                const float* zr = z + ((size_t)((s * 8 + bis[n]) * T_ + sis[n] + kshift)) * ZD;
                float4 na = *(const float4*)(zr + 4 * lg);
                float4 nb = *(const float4*)(zr + 32 + 4 * lg);
                float d = wa.x * na.x + wa.y * na.y + wa.z * na.z + wa.w * na.w
                        + wb.x * nb.x + wb.y * nb.y + wb.z * nb.z + wb.w * nb.w;
                d += __shfl_xor_sync(gmask, d, 1);
                d += __shfl_xor_sync(gmask, d, 2);
                d += __shfl_xor_sync(gmask, d, 4);
                d *= 0.125f;
                if (d > pos) ok = 0.0f;                 // argmax==0 iff pos >= all negs
                if (d > m) { ssum = ssum * __expf(m - d) + 1.0f; m = d; }
                else       { ssum += __expf(d - m); }
            }

            lts[kh] += m + __logf(ssum) - pos;          // log_z - f0
            oks[kh] += ok;
        }
    }

    // cross-group reduce within warp (all lanes reconverged; values uniform per group)
#pragma unroll
    for (int kh = 0; kh < 2; kh++) {
        lts[kh] += __shfl_xor_sync(0xffffffffu, lts[kh], 8);
        lts[kh] += __shfl_xor_sync(0xffffffffu, lts[kh], 16);
        oks[kh] += __shfl_xor_sync(0xffffffffu, oks[kh], 8);
        oks[kh] += __shfl_xor_sync(0xffffffffu, oks[kh], 16);
    }

    __shared__ float sred[8][4];
    if (lane == 0) {
        sred[wid][0] = lts[0]; sred[wid][1] = lts[1];
        sred[wid][2] = oks[0]; sred[wid][3] = oks[1];
    }
    __syncthreads();
    if (tid == 0) {
        float L0 = 0.f, L1 = 0.f, A0 = 0.f, A1 = 0.f;
#pragma unroll
        for (int i = 0; i < 8; i++) {
            L0 += sred[i][0]; L1 += sred[i][1];
            A0 += sred[i][2]; A1 += sred[i][3];
        }
        atomicAdd(&g_loss[k0],     (double)L0);
        atomicAdd(&g_loss[k0 + 1], (double)L1);
        atomicAdd(&g_acc[k0],      (double)A0);
        atomicAdd(&g_acc[k0 + 1],  (double)A1);
    }
}

// ================= finalize =================
__global__ void finalize(float* __restrict__ out, int out_size) {
    if (threadIdx.x == 0) {
        double tot = 0.0;
#pragma unroll
        for (int kk = 0; kk < K_; kk++) tot += g_loss[kk];
        if (out_size > 0) out[0] = (float)(tot / ((double)K_ * (double)TOTPOS));
#pragma unroll
        for (int kk = 0; kk < K_; kk++)
            if (1 + kk < out_size) out[1 + kk] = (float)(g_acc[kk] / (double)TOTPOS);
    }
}

// ---------------- launch ----------------
extern "C" void kernel_launch(void* const* d_in, const int* in_sizes, int n_in,
                              void* d_out, int out_size) {
    const float* z  = (const float*)d_in[0];
    const float* c  = (const float*)d_in[1];
    const float* W  = (const float*)d_in[2];
    const float* b  = (const float*)d_in[3];
    const int* bidx = (const int*)d_in[4];
    const int* sidx = (const int*)d_in[5];

    cudaFuncSetAttribute(fused_gemm_loss, cudaFuncAttributeMaxDynamicSharedMemorySize,
                         SMEM_BYTES);

    zero_accum<<<1, 32>>>();

    dim3 grid(K_ / 2, 9, SU);   // (kpair, l-tile, su); kpair fastest for A-tile L2 reuse
    fused_gemm_loss<<<grid, 256, SMEM_BYTES>>>(c, W, b, z, bidx, sidx);

    finalize<<<1, 32>>>((float*)d_out, out_size);
}